// round 12
// baseline (speedup 1.0000x reference)
#include <cuda_runtime.h>
#include <cuda_bf16.h>
#include <cuda_fp16.h>
#include <math.h>

// Problem constants
#define PP   256
#define FF   20
#define HH   18
#define WW   18
#define HW   (HH*WW)      // 324
#define VOL  (FF*HH*WW)   // 6480
#define MAXB 4096
#define PI_F 3.14159f

// Sampler pair volume: per layer 21 rows x 21 half2, 20 layers
#define PROW 21
#define PLAY (PROW*PROW)  // 441
#define PVOL (FF*PLAY)    // 8820 half2 = 35280 B

// Head partials: 4 k-groups x B rows x 80 cols (fp32)
#define NG 4
__device__ float g_part[NG][MAXB * 80];

// ---------------------------------------------------------------------------
// f32x2 helpers (FFMA2 via PTX)
// ---------------------------------------------------------------------------
typedef unsigned long long u64;

__device__ __forceinline__ u64 pack2(float lo, float hi) {
    u64 d;
    asm("mov.b64 %0, {%1, %2};" : "=l"(d)
        : "r"(__float_as_uint(lo)), "r"(__float_as_uint(hi)));
    return d;
}
__device__ __forceinline__ u64 pack2dup(float v) {
    u64 d;
    asm("mov.b64 %0, {%1, %1};" : "=l"(d) : "r"(__float_as_uint(v)));
    return d;
}
__device__ __forceinline__ u64 fma2(u64 a, u64 b, u64 c) {
    u64 d;
    asm("fma.rn.f32x2 %0, %1, %2, %3;" : "=l"(d) : "l"(a), "l"(b), "l"(c));
    return d;
}
__device__ __forceinline__ float2 unpack2(u64 v) {
    unsigned lo, hi;
    asm("mov.b64 {%0, %1}, %2;" : "=r"(lo), "=r"(hi) : "l"(v));
    float2 f; f.x = __uint_as_float(lo); f.y = __uint_as_float(hi);
    return f;
}

// ---------------------------------------------------------------------------
// Kernel 1: fused hidden + head partials.
// Main: h_tile[64 rows][64 cols] = relu(pc @ W1 + b1) slice.
// Epilogue: g_part[n0g][row][80] = h_tile @ Whead[n0..n0+64][80].
// grid = (B/64, 4), 256 threads.
// ---------------------------------------------------------------------------
#define K1_BM 64
#define K1_BN 64
#define K1_BK 32
#define K1_AS 68
#define HS_S  66      // h-tile smem stride

__global__ __launch_bounds__(256) void adaat_hidden_kernel(
    const float* __restrict__ pc, int B,
    const float* __restrict__ W1, const float* __restrict__ b1,
    const float* __restrict__ Ws, const float* __restrict__ Wr,
    const float* __restrict__ Wt)
{
    // pool: main loop uses As = pool[0:2176), Bs = pool[2176:4352)
    //       epilogue reuses pool as hs[col][row] (64*66 = 4224 floats)
    __shared__ float pool[4352];
    __shared__ float Wh[64 * 80];     // head-weight slice (20.5 KB)
    float* As = pool;
    float* Bs = pool + K1_BK * K1_AS;

    const int b0  = blockIdx.x * K1_BM;
    const int n0  = blockIdx.y * K1_BN;
    const int tid = threadIdx.x;
    const int tc  = tid & 15;
    const int tr  = tid >> 4;

    // stage head-weight slice: Wh[kk][c], kk = local k (h col), c = head col
    #pragma unroll
    for (int p = 0; p < 20; p++) {
        int i  = p * 256 + tid;
        int kk = i / 80;
        int c  = i - kk * 80;
        int gk = n0 + kk;
        float v;
        if (c < 20)      v = Ws[(size_t)gk * 20 + c];
        else if (c < 40) v = Wr[(size_t)gk * 20 + (c - 20)];
        else             v = Wt[(size_t)gk * 40 + (c - 40)];
        Wh[kk * 80 + c] = v;
    }

    // ---- main GEMM ----
    u64 acc[4][2];
    {
        float4 bj = *(const float4*)(b1 + n0 + tc * 4);
        u64 lo = pack2(bj.x, bj.y), hi = pack2(bj.z, bj.w);
        #pragma unroll
        for (int i = 0; i < 4; i++) { acc[i][0] = lo; acc[i][1] = hi; }
    }

    for (int kt = 0; kt < PP; kt += K1_BK) {
        #pragma unroll
        for (int p = 0; p < 8; p++) {
            int idx = p * 256 + tid;
            int row = idx >> 5;
            int kk  = idx & 31;
            float v = (b0 + row < B) ? pc[(size_t)(b0 + row) * PP + kt + kk] : 0.f;
            As[kk * K1_AS + row] = v;
        }
        #pragma unroll
        for (int p = 0; p < 8; p++) {
            int idx = p * 256 + tid;
            int kk  = idx >> 6;
            int col = idx & 63;
            Bs[kk * K1_AS + col] = W1[(size_t)(kt + kk) * PP + n0 + col];
        }
        __syncthreads();

        #pragma unroll
        for (int kk = 0; kk < K1_BK; kk++) {
            float4 a = *(const float4*)(As + kk * K1_AS + tr * 4);
            float4 w = *(const float4*)(Bs + kk * K1_AS + tc * 4);
            u64 wlo = pack2(w.x, w.y), whi = pack2(w.z, w.w);
            u64 a0 = pack2dup(a.x), a1 = pack2dup(a.y);
            u64 a2 = pack2dup(a.z), a3 = pack2dup(a.w);
            acc[0][0] = fma2(a0, wlo, acc[0][0]); acc[0][1] = fma2(a0, whi, acc[0][1]);
            acc[1][0] = fma2(a1, wlo, acc[1][0]); acc[1][1] = fma2(a1, whi, acc[1][1]);
            acc[2][0] = fma2(a2, wlo, acc[2][0]); acc[2][1] = fma2(a2, whi, acc[2][1]);
            acc[3][0] = fma2(a3, wlo, acc[3][0]); acc[3][1] = fma2(a3, whi, acc[3][1]);
        }
        __syncthreads();
    }

    // ---- relu + spill h tile to smem: hs[col][row] ----
    float* hs = pool;
    #pragma unroll
    for (int i = 0; i < 4; i++) {
        float2 v0 = unpack2(acc[i][0]);
        float2 v1 = unpack2(acc[i][1]);
        int row = tr * 4 + i;
        hs[(tc * 4 + 0) * HS_S + row] = fmaxf(v0.x, 0.f);
        hs[(tc * 4 + 1) * HS_S + row] = fmaxf(v0.y, 0.f);
        hs[(tc * 4 + 2) * HS_S + row] = fmaxf(v1.x, 0.f);
        hs[(tc * 4 + 3) * HS_S + row] = fmaxf(v1.y, 0.f);
    }
    __syncthreads();

    // ---- head partials: out[row][80] = hs[:, row] . Wh[:, :] over 64 local k
    // thread: row = tid>>2 (0..63), quarter q = tid&3 -> cols q*20..q*20+19
    // unroll kept at 2: 4x batching spilled accp[] (R11 lesson).
    {
        const int row = tid >> 2;
        const int q   = tid & 3;
        float accp[20];
        #pragma unroll
        for (int j = 0; j < 20; j++) accp[j] = 0.f;

        #pragma unroll 2
        for (int kk = 0; kk < 64; kk++) {
            float hv = hs[kk * HS_S + row];
            const float* wrow = Wh + kk * 80 + q * 20;
            #pragma unroll
            for (int g = 0; g < 5; g++) {
                float4 w = *(const float4*)(wrow + g * 4);
                accp[g*4+0] = fmaf(hv, w.x, accp[g*4+0]);
                accp[g*4+1] = fmaf(hv, w.y, accp[g*4+1]);
                accp[g*4+2] = fmaf(hv, w.z, accp[g*4+2]);
                accp[g*4+3] = fmaf(hv, w.w, accp[g*4+3]);
            }
        }

        if (b0 + row < B) {
            float* dst = g_part[blockIdx.y] + (size_t)(b0 + row) * 80 + q * 20;
            #pragma unroll
            for (int g = 0; g < 5; g++)
                *(float4*)(dst + g * 4) =
                    make_float4(accp[g*4+0], accp[g*4+1], accp[g*4+2], accp[g*4+3]);
        }
    }
}

// ---------------------------------------------------------------------------
// Kernel 2: trilinear sample. Border-only zeroing (rows py 0/19/20, col 19),
// merged with fill; single barrier. Body is the R4-proven sampler.
// ---------------------------------------------------------------------------
__global__ __launch_bounds__(324) void adaat_sample_kernel(
    const float* __restrict__ fm, float* __restrict__ out,
    const float* __restrict__ bs, const float* __restrict__ br,
    const float* __restrict__ bt)
{
    const int b   = blockIdx.x;
    const int tx  = threadIdx.x;      // 0..17
    const int ty  = threadIdx.y;      // 0..17
    const int tid = ty * WW + tx;

    __shared__ __half2 pairs[PVOL];   // 35280 B
    __shared__ float4  cfA[FF];       // axx, axy, cx, zw0
    __shared__ float4  cfB[FF];       // ayx, ayy, cy, zw1
    __shared__ int2    zb[FF];

    const __half2 hzero = __floats2half2_rn(0.f, 0.f);

    // zero border rows py = 0, 19, 20 (all 21 cols): 20 layers x 63 cells
    for (int i = tid; i < FF * 63; i += HW) {
        int z = i / 63;
        int j = i - z * 63;
        int r = (j < 21) ? 0 : ((j < 42) ? 19 : 20);
        int c = (j < 21) ? j : ((j < 42) ? (j - 21) : (j - 42));
        pairs[z * PLAY + r * PROW + c] = hzero;
    }
    // zero border col 19 rows 1..18: 20 layers x 18 cells
    for (int i = tid; i < FF * 18; i += HW) {
        int z = i / 18;
        int r = 1 + (i - z * 18);
        pairs[z * PLAY + r * PROW + 19] = hzero;
    }

    // fill interior: pairs[z][ty+1][tx+1] = (V(tx), V(tx+1)); col 0 = (0, V(0))
    {
        const float* src = fm + (size_t)b * VOL + ty * WW + tx;
        __half2* dst = pairs + (ty + 1) * PROW + (tx + 1);
        #pragma unroll
        for (int z = 0; z < FF; z++) {
            float val   = src[z * HW];
            float right = (tx < WW - 1) ? src[z * HW + 1] : 0.f;
            dst[z * PLAY] = __floats2half2_rn(val, right);
            if (tx == 0)
                pairs[z * PLAY + (ty + 1) * PROW] = __floats2half2_rn(0.f, val);
        }
    }

    if (tid < FF) {
        const int f = tid;
        // sum head partials + bias, then activations
        float rs  = bs[f];
        float rr  = br[f];
        float rtx = bt[2 * f];
        float rty = bt[2 * f + 1];
        #pragma unroll
        for (int p = 0; p < NG; p++) {
            const float* pp = g_part[p] + (size_t)b * 80;
            rs  += pp[f];
            rr  += pp[20 + f];
            rtx += pp[40 + 2 * f];
            rty += pp[41 + 2 * f];
        }
        float sc  = 2.f / (1.f + expf(-rs));
        float ang = tanhf(rr) * PI_F;
        float c   = cosf(ang), s = sinf(ang);
        float txp = tanhf(rtx), typ = tanhf(rty);

        float kk  = sc * ((float)WW / (WW - 1));
        float axx = c * kk,  axy = -s * kk;
        float ayx = s * kk,  ayy =  c * kk;
        float cx = (WW * 0.5f) * (txp - sc * c + sc * s) + (WW - 1) * 0.5f;
        float cy = (HH * 0.5f) * (typ - sc * s - sc * c) + (HH - 1) * 0.5f;

        float iz  = (float)f * ((float)FF / (FF - 1)) - 0.5f;
        float z0f = floorf(iz);
        float wz  = iz - z0f;
        int   z0  = (int)z0f, z1 = z0 + 1;
        float w0  = (z0 >= 0 && z0 < FF) ? (1.f - wz) : 0.f;
        float w1  = (z1 >= 0 && z1 < FF) ? wz         : 0.f;
        int   zb0 = min(max(z0, 0), FF - 1) * PLAY;
        int   zb1 = min(max(z1, 0), FF - 1) * PLAY;

        cfA[f] = make_float4(axx, axy, cx, w0);
        cfB[f] = make_float4(ayx, ayy, cy, w1);
        zb[f]  = make_int2(zb0, zb1);
    }
    __syncthreads();

    const float fx = (float)tx, fy = (float)ty;
    float* outb = out + (size_t)b * VOL + tid;

    #pragma unroll 4
    for (int f = 0; f < FF; f++) {
        float4 A  = cfA[f];
        float4 Bv = cfB[f];
        int2   zo = zb[f];

        float ix = fmaf(A.x,  fx, fmaf(A.y,  fy, A.z));
        float iy = fmaf(Bv.x, fx, fmaf(Bv.y, fy, Bv.z));
        ix = fminf(fmaxf(ix, -1.f), (float)WW);
        iy = fminf(fmaxf(iy, -1.f), (float)HH);

        int   x0 = __float2int_rd(ix);
        int   y0 = __float2int_rd(iy);
        float wx = ix - (float)x0;
        float wy = iy - (float)y0;

        int bo = y0 * PROW + x0 + (PROW + 1);

        float2 f00 = __half22float2(pairs[zo.x + bo]);
        float2 f01 = __half22float2(pairs[zo.x + bo + PROW]);
        float2 f10 = __half22float2(pairs[zo.y + bo]);
        float2 f11 = __half22float2(pairs[zo.y + bo + PROW]);

        float h00 = fmaf(wx, f00.y - f00.x, f00.x);
        float h01 = fmaf(wx, f01.y - f01.x, f01.x);
        float h10 = fmaf(wx, f10.y - f10.x, f10.x);
        float h11 = fmaf(wx, f11.y - f11.x, f11.x);

        float s0 = fmaf(wy, h01 - h00, h00);
        float s1 = fmaf(wy, h11 - h10, h10);

        outb[f * HW] = fmaf(A.w, s0, Bv.w * s1);
    }
}

// ---------------------------------------------------------------------------
// Launch
// ---------------------------------------------------------------------------
extern "C" void kernel_launch(void* const* d_in, const int* in_sizes, int n_in,
                              void* d_out, int out_size)
{
    const float* feature_map = (const float*)d_in[0];
    const float* para_code   = (const float*)d_in[1];
    const float* W1          = (const float*)d_in[2];
    const float* b1          = (const float*)d_in[3];
    const float* Ws          = (const float*)d_in[4];
    const float* bs          = (const float*)d_in[5];
    const float* Wr          = (const float*)d_in[6];
    const float* br          = (const float*)d_in[7];
    const float* Wt          = (const float*)d_in[8];
    const float* bt          = (const float*)d_in[9];
    float*       out         = (float*)d_out;

    int B = in_sizes[1] / PP;
    if (B > MAXB) B = MAXB;

    dim3 g1((B + K1_BM - 1) / K1_BM, NG);
    adaat_hidden_kernel<<<g1, 256>>>(para_code, B, W1, b1, Ws, Wr, Wt);
    adaat_sample_kernel<<<B, dim3(WW, HH)>>>(feature_map, out, bs, br, bt);
}

// round 13
// speedup vs baseline: 1.0693x; 1.0693x over previous
#include <cuda_runtime.h>
#include <cuda_bf16.h>
#include <cuda_fp16.h>
#include <math.h>

// Problem constants
#define PP   256
#define FF   20
#define HH   18
#define WW   18
#define HW   (HH*WW)      // 324
#define VOL  (FF*HH*WW)   // 6480
#define MAXB 4096
#define PI_F 3.14159f

// Sampler pair volume: per layer 21 rows x 21 half2, 20 layers
#define PROW 21
#define PLAY (PROW*PROW)  // 441
#define PVOL (FF*PLAY)    // 8820 half2 = 35280 B

// Device scratch
#define NG 4
__device__ float g_h[MAXB * PP];            // hidden activations
__device__ float g_part[NG][MAXB * 80];     // head partials per k-group

// ---------------------------------------------------------------------------
// f32x2 helpers (FFMA2 via PTX)
// ---------------------------------------------------------------------------
typedef unsigned long long u64;

__device__ __forceinline__ u64 pack2(float lo, float hi) {
    u64 d;
    asm("mov.b64 %0, {%1, %2};" : "=l"(d)
        : "r"(__float_as_uint(lo)), "r"(__float_as_uint(hi)));
    return d;
}
__device__ __forceinline__ u64 pack2dup(float v) {
    u64 d;
    asm("mov.b64 %0, {%1, %1};" : "=l"(d) : "r"(__float_as_uint(v)));
    return d;
}
__device__ __forceinline__ u64 fma2(u64 a, u64 b, u64 c) {
    u64 d;
    asm("fma.rn.f32x2 %0, %1, %2, %3;" : "=l"(d) : "l"(a), "l"(b), "l"(c));
    return d;
}
__device__ __forceinline__ float2 unpack2(u64 v) {
    unsigned lo, hi;
    asm("mov.b64 {%0, %1}, %2;" : "=r"(lo), "=r"(hi) : "l"(v));
    float2 f; f.x = __uint_as_float(lo); f.y = __uint_as_float(hi);
    return f;
}

// ---------------------------------------------------------------------------
// Kernel 1: h = relu(pc @ W1 + b1), double-buffered tiled SGEMM.
// BM=64, BN=64, BK=32, 256 threads, 4x4 thread tile, grid (B/64, 4).
// ---------------------------------------------------------------------------
#define K1_BM 64
#define K1_BN 64
#define K1_BK 32
#define K1_AS 68
#define NKT   (PP / K1_BK)   // 8

__global__ __launch_bounds__(256) void adaat_hidden_kernel(
    const float* __restrict__ pc, int B,
    const float* __restrict__ W1, const float* __restrict__ b1)
{
    __shared__ float As[2][K1_BK * K1_AS];   // 2 x 8704 B
    __shared__ float Bs[2][K1_BK * K1_AS];

    const int b0  = blockIdx.x * K1_BM;
    const int n0  = blockIdx.y * K1_BN;
    const int tid = threadIdx.x;
    const int tc  = tid & 15;
    const int tr  = tid >> 4;

    float ra[8], rb[8];

    // prefetch tile 0 -> regs -> smem buf 0
    #pragma unroll
    for (int p = 0; p < 8; p++) {
        int idx = p * 256 + tid;
        int row = idx >> 5, kk = idx & 31;
        ra[p] = (b0 + row < B) ? pc[(size_t)(b0 + row) * PP + kk] : 0.f;
    }
    #pragma unroll
    for (int p = 0; p < 8; p++) {
        int idx = p * 256 + tid;
        int kk = idx >> 6, col = idx & 63;
        rb[p] = W1[(size_t)kk * PP + n0 + col];
    }
    #pragma unroll
    for (int p = 0; p < 8; p++) {
        int idx = p * 256 + tid;
        int row = idx >> 5, kk = idx & 31;
        As[0][kk * K1_AS + row] = ra[p];
    }
    #pragma unroll
    for (int p = 0; p < 8; p++) {
        int idx = p * 256 + tid;
        int kk = idx >> 6, col = idx & 63;
        Bs[0][kk * K1_AS + col] = rb[p];
    }
    __syncthreads();

    u64 acc[4][2];
    {
        float4 bj = *(const float4*)(b1 + n0 + tc * 4);
        u64 lo = pack2(bj.x, bj.y), hi = pack2(bj.z, bj.w);
        #pragma unroll
        for (int i = 0; i < 4; i++) { acc[i][0] = lo; acc[i][1] = hi; }
    }

    for (int it = 0; it < NKT; it++) {
        const int cur = it & 1;
        const int nxt = cur ^ 1;

        if (it < NKT - 1) {
            int kt = (it + 1) * K1_BK;
            #pragma unroll
            for (int p = 0; p < 8; p++) {
                int idx = p * 256 + tid;
                int row = idx >> 5, kk = idx & 31;
                ra[p] = (b0 + row < B) ? pc[(size_t)(b0 + row) * PP + kt + kk] : 0.f;
            }
            #pragma unroll
            for (int p = 0; p < 8; p++) {
                int idx = p * 256 + tid;
                int kk = idx >> 6, col = idx & 63;
                rb[p] = W1[(size_t)(kt + kk) * PP + n0 + col];
            }
        }

        #pragma unroll
        for (int kk = 0; kk < K1_BK; kk++) {
            float4 a = *(const float4*)(&As[cur][kk * K1_AS + tr * 4]);
            float4 w = *(const float4*)(&Bs[cur][kk * K1_AS + tc * 4]);
            u64 wlo = pack2(w.x, w.y), whi = pack2(w.z, w.w);
            u64 a0 = pack2dup(a.x), a1 = pack2dup(a.y);
            u64 a2 = pack2dup(a.z), a3 = pack2dup(a.w);
            acc[0][0] = fma2(a0, wlo, acc[0][0]); acc[0][1] = fma2(a0, whi, acc[0][1]);
            acc[1][0] = fma2(a1, wlo, acc[1][0]); acc[1][1] = fma2(a1, whi, acc[1][1]);
            acc[2][0] = fma2(a2, wlo, acc[2][0]); acc[2][1] = fma2(a2, whi, acc[2][1]);
            acc[3][0] = fma2(a3, wlo, acc[3][0]); acc[3][1] = fma2(a3, whi, acc[3][1]);
        }

        if (it < NKT - 1) {
            #pragma unroll
            for (int p = 0; p < 8; p++) {
                int idx = p * 256 + tid;
                int row = idx >> 5, kk = idx & 31;
                As[nxt][kk * K1_AS + row] = ra[p];
            }
            #pragma unroll
            for (int p = 0; p < 8; p++) {
                int idx = p * 256 + tid;
                int kk = idx >> 6, col = idx & 63;
                Bs[nxt][kk * K1_AS + col] = rb[p];
            }
        }
        __syncthreads();
    }

    #pragma unroll
    for (int i = 0; i < 4; i++) {
        int row = b0 + tr * 4 + i;
        if (row >= B) break;
        float2 v0 = unpack2(acc[i][0]);
        float2 v1 = unpack2(acc[i][1]);
        float4 o;
        o.x = fmaxf(v0.x, 0.f); o.y = fmaxf(v0.y, 0.f);
        o.z = fmaxf(v1.x, 0.f); o.w = fmaxf(v1.y, 0.f);
        *(float4*)(g_h + (size_t)row * PP + n0 + tc * 4) = o;
    }
}

// ---------------------------------------------------------------------------
// Kernel 2: head partials, k-split. grid (B/64, 4), 256 threads.
// Block (bx, g): g_part[g][row][80] = h[row][g*64 .. g*64+63] @ Wh-slice.
// ---------------------------------------------------------------------------
#define HS_S 66

__global__ __launch_bounds__(256) void adaat_heads_kernel(
    int B,
    const float* __restrict__ Ws, const float* __restrict__ Wr,
    const float* __restrict__ Wt)
{
    __shared__ float hsl[64 * HS_S];   // [kk][row], 16896 B
    __shared__ float Wh[64 * 80];      // 20480 B

    const int b0  = blockIdx.x * 64;
    const int g   = blockIdx.y;
    const int tid = threadIdx.x;

    // stage h slice: g_h[(b0+row)*PP + g*64 + kk] -> hsl[kk][row]
    #pragma unroll
    for (int p = 0; p < 16; p++) {
        int idx = p * 256 + tid;
        int row = idx >> 6, kk = idx & 63;
        float v = (b0 + row < B) ? g_h[(size_t)(b0 + row) * PP + g * 64 + kk] : 0.f;
        hsl[kk * HS_S + row] = v;
    }
    // stage head-weight slice: Wh[kk][c]
    #pragma unroll
    for (int p = 0; p < 20; p++) {
        int i  = p * 256 + tid;
        int kk = i / 80;
        int c  = i - kk * 80;
        int gk = g * 64 + kk;
        float v;
        if (c < 20)      v = Ws[(size_t)gk * 20 + c];
        else if (c < 40) v = Wr[(size_t)gk * 20 + (c - 20)];
        else             v = Wt[(size_t)gk * 40 + (c - 40)];
        Wh[kk * 80 + c] = v;
    }
    __syncthreads();

    const int row = tid >> 2;
    const int q   = tid & 3;
    float accp[20];
    #pragma unroll
    for (int j = 0; j < 20; j++) accp[j] = 0.f;

    #pragma unroll 2
    for (int kk = 0; kk < 64; kk++) {
        float hv = hsl[kk * HS_S + row];
        const float* wrow = Wh + kk * 80 + q * 20;
        #pragma unroll
        for (int gg = 0; gg < 5; gg++) {
            float4 w = *(const float4*)(wrow + gg * 4);
            accp[gg*4+0] = fmaf(hv, w.x, accp[gg*4+0]);
            accp[gg*4+1] = fmaf(hv, w.y, accp[gg*4+1]);
            accp[gg*4+2] = fmaf(hv, w.z, accp[gg*4+2]);
            accp[gg*4+3] = fmaf(hv, w.w, accp[gg*4+3]);
        }
    }

    if (b0 + row < B) {
        float* dst = g_part[g] + (size_t)(b0 + row) * 80 + q * 20;
        #pragma unroll
        for (int gg = 0; gg < 5; gg++)
            *(float4*)(dst + gg * 4) =
                make_float4(accp[gg*4+0], accp[gg*4+1], accp[gg*4+2], accp[gg*4+3]);
    }
}

// ---------------------------------------------------------------------------
// Kernel 3: trilinear sample — R11-exact (proven 72.7 us). One CTA per batch,
// block (18,18). Coefficient setup sums partials + biases + activations.
// ---------------------------------------------------------------------------
__global__ __launch_bounds__(324) void adaat_sample_kernel(
    const float* __restrict__ fm, float* __restrict__ out,
    const float* __restrict__ bs, const float* __restrict__ br,
    const float* __restrict__ bt)
{
    const int b   = blockIdx.x;
    const int tx  = threadIdx.x;      // 0..17
    const int ty  = threadIdx.y;      // 0..17
    const int tid = ty * WW + tx;

    __shared__ __half2 pairs[PVOL];   // 35280 B
    __shared__ float4  cfA[FF];       // axx, axy, cx, zw0
    __shared__ float4  cfB[FF];       // ayx, ayy, cy, zw1
    __shared__ int2    zb[FF];

    {
        float4* p4 = (float4*)pairs;
        for (int i = tid; i < PVOL / 4; i += HW)
            p4[i] = make_float4(0.f, 0.f, 0.f, 0.f);
    }
    __syncthreads();

    {
        const float* src = fm + (size_t)b * VOL + ty * WW + tx;
        __half2* dst = pairs + (ty + 1) * PROW + (tx + 1);
        #pragma unroll
        for (int z = 0; z < FF; z++) {
            float val   = src[z * HW];
            float right = (tx < WW - 1) ? src[z * HW + 1] : 0.f;
            dst[z * PLAY] = __floats2half2_rn(val, right);
            if (tx == 0)
                pairs[z * PLAY + (ty + 1) * PROW] = __floats2half2_rn(0.f, val);
        }
    }

    if (tid < FF) {
        const int f = tid;
        float rs  = bs[f];
        float rr  = br[f];
        float rtx = bt[2 * f];
        float rty = bt[2 * f + 1];
        #pragma unroll
        for (int p = 0; p < NG; p++) {
            const float* pp = g_part[p] + (size_t)b * 80;
            rs  += pp[f];
            rr  += pp[20 + f];
            rtx += pp[40 + 2 * f];
            rty += pp[41 + 2 * f];
        }
        float sc  = 2.f / (1.f + expf(-rs));
        float ang = tanhf(rr) * PI_F;
        float c   = cosf(ang), s = sinf(ang);
        float txp = tanhf(rtx), typ = tanhf(rty);

        float kk  = sc * ((float)WW / (WW - 1));
        float axx = c * kk,  axy = -s * kk;
        float ayx = s * kk,  ayy =  c * kk;
        float cx = (WW * 0.5f) * (txp - sc * c + sc * s) + (WW - 1) * 0.5f;
        float cy = (HH * 0.5f) * (typ - sc * s - sc * c) + (HH - 1) * 0.5f;

        float iz  = (float)f * ((float)FF / (FF - 1)) - 0.5f;
        float z0f = floorf(iz);
        float wz  = iz - z0f;
        int   z0  = (int)z0f, z1 = z0 + 1;
        float w0  = (z0 >= 0 && z0 < FF) ? (1.f - wz) : 0.f;
        float w1  = (z1 >= 0 && z1 < FF) ? wz         : 0.f;
        int   zb0 = min(max(z0, 0), FF - 1) * PLAY;
        int   zb1 = min(max(z1, 0), FF - 1) * PLAY;

        cfA[f] = make_float4(axx, axy, cx, w0);
        cfB[f] = make_float4(ayx, ayy, cy, w1);
        zb[f]  = make_int2(zb0, zb1);
    }
    __syncthreads();

    const float fx = (float)tx, fy = (float)ty;
    float* outb = out + (size_t)b * VOL + tid;

    #pragma unroll 4
    for (int f = 0; f < FF; f++) {
        float4 A  = cfA[f];
        float4 Bv = cfB[f];
        int2   zo = zb[f];

        float ix = fmaf(A.x,  fx, fmaf(A.y,  fy, A.z));
        float iy = fmaf(Bv.x, fx, fmaf(Bv.y, fy, Bv.z));
        ix = fminf(fmaxf(ix, -1.f), (float)WW);
        iy = fminf(fmaxf(iy, -1.f), (float)HH);

        int   x0 = __float2int_rd(ix);
        int   y0 = __float2int_rd(iy);
        float wx = ix - (float)x0;
        float wy = iy - (float)y0;

        int bo = y0 * PROW + x0 + (PROW + 1);

        float2 f00 = __half22float2(pairs[zo.x + bo]);
        float2 f01 = __half22float2(pairs[zo.x + bo + PROW]);
        float2 f10 = __half22float2(pairs[zo.y + bo]);
        float2 f11 = __half22float2(pairs[zo.y + bo + PROW]);

        float h00 = fmaf(wx, f00.y - f00.x, f00.x);
        float h01 = fmaf(wx, f01.y - f01.x, f01.x);
        float h10 = fmaf(wx, f10.y - f10.x, f10.x);
        float h11 = fmaf(wx, f11.y - f11.x, f11.x);

        float s0 = fmaf(wy, h01 - h00, h00);
        float s1 = fmaf(wy, h11 - h10, h10);

        outb[f * HW] = fmaf(A.w, s0, Bv.w * s1);
    }
}

// ---------------------------------------------------------------------------
// Launch
// ---------------------------------------------------------------------------
extern "C" void kernel_launch(void* const* d_in, const int* in_sizes, int n_in,
                              void* d_out, int out_size)
{
    const float* feature_map = (const float*)d_in[0];
    const float* para_code   = (const float*)d_in[1];
    const float* W1          = (const float*)d_in[2];
    const float* b1          = (const float*)d_in[3];
    const float* Ws          = (const float*)d_in[4];
    const float* bs          = (const float*)d_in[5];
    const float* Wr          = (const float*)d_in[6];
    const float* br          = (const float*)d_in[7];
    const float* Wt          = (const float*)d_in[8];
    const float* bt          = (const float*)d_in[9];
    float*       out         = (float*)d_out;

    int B = in_sizes[1] / PP;
    if (B > MAXB) B = MAXB;

    dim3 g1((B + K1_BM - 1) / K1_BM, NG);
    adaat_hidden_kernel<<<g1, 256>>>(para_code, B, W1, b1);
    adaat_heads_kernel<<<g1, 256>>>(B, Ws, Wr, Wt);
    adaat_sample_kernel<<<B, dim3(WW, HH)>>>(feature_map, out, bs, br, bt);
}